// round 3
// baseline (speedup 1.0000x reference)
#include <cuda_runtime.h>
#include <cstddef>

#define T_STEPS 512
#define B_SZ 256
#define I_SZ 64
#define N_SZ 512
#define C_SZ 10
#define ALPHA 0.5f
#define INV_TAU 0.5f
#define SLOPE 0.01f
#define NN (N_SZ * N_SZ)

// grid: 128 CTAs = 8 rowblocks x 16 colblocks; tile 32x32; 256 threads; micro 2x2
#define G_CTAS 128
#define KC 128                    // k-chunk
#define A_STRIDE 68               // duplicated A row: 64 floats + 4 pad
#define W_STRIDE 32
#define A_BUF (KC * A_STRIDE)     // 8704 floats
#define W_BUF (KC * W_STRIDE)     // 4096 floats
#define SMEM_FLOATS (2 * A_BUF + 2 * W_BUF)
#define SMEM_BYTES (SMEM_FLOATS * 4)

typedef unsigned long long u64;

// ---------------- device scratch ----------------
__device__ float g_x[(size_t)T_STEPS * B_SZ * N_SZ];   // x = data@Win + b_in
__device__ float g_W[5 * NN];                          // W0,W1,W2(diag=0), Wi0, Wi1
__device__ float g_bias[3 * N_SZ];
__device__ float g_h[2][3][B_SZ * N_SZ];
__device__ unsigned g_rb[8];                           // per-rowblock arrival counters

// ---------------- f32x2 helpers ----------------
__device__ __forceinline__ void fma2(u64& d, u64 a, u64 b) {
    asm("fma.rn.f32x2 %0, %1, %2, %0;" : "+l"(d) : "l"(a), "l"(b));
}
__device__ __forceinline__ float2 unpack2(u64 v) {
    float2 r;
    asm("mov.b64 {%0, %1}, %2;" : "=f"(r.x), "=f"(r.y) : "l"(v));
    return r;
}

// ---------------- prep ----------------
__global__ void prep_kernel(const float* __restrict__ Whh, const float* __restrict__ bhh,
                            const float* __restrict__ Whi, const float* __restrict__ bhi,
                            const float* __restrict__ h0) {
    int idx = blockIdx.x * blockDim.x + threadIdx.x;
    if (idx < 3 * NN) {
        int rc = idx % NN;
        int r = rc / N_SZ, c = rc % N_SZ;
        g_W[idx] = (r == c) ? 0.0f : Whh[idx];
    }
    if (idx < 2 * NN) g_W[3 * NN + idx] = Whi[idx];
    if (idx < 3 * N_SZ) {
        int l = idx / N_SZ, c = idx % N_SZ;
        float b = bhh[idx];
        if (l >= 1) b += bhi[(l - 1) * N_SZ + c];
        g_bias[idx] = b;
    }
    if (idx < 3 * B_SZ * N_SZ) {
        int l = idx / (B_SZ * N_SZ);
        g_h[0][l][idx % (B_SZ * N_SZ)] = h0[idx];
    }
    if (idx < 8) g_rb[idx] = 0;
}

// ---------------- input projection (as R1, works fine) ----------------
__global__ void __launch_bounds__(256) xproj_kernel(const float* __restrict__ data,
                                                    const float* __restrict__ Win,
                                                    const float* __restrict__ bin) {
    __shared__ float Ask[64][65];
    __shared__ float Ws[64][34];
    const int row0 = blockIdx.x * 64;
    const int col0 = blockIdx.y * 32;
    const int tid = threadIdx.x;
    {
        int ar = tid >> 2, ak = (tid & 3) * 4;
        #pragma unroll
        for (int it = 0; it < 4; ++it) {
            float4 v = *(const float4*)(data + (size_t)(row0 + ar) * I_SZ + ak + it * 16);
            Ask[ak + it * 16 + 0][ar] = v.x;
            Ask[ak + it * 16 + 1][ar] = v.y;
            Ask[ak + it * 16 + 2][ar] = v.z;
            Ask[ak + it * 16 + 3][ar] = v.w;
        }
    }
    {
        int wk = tid >> 3, wc = (tid & 7) * 4;
        #pragma unroll
        for (int it = 0; it < 2; ++it) {
            float4 v = *(const float4*)(Win + (size_t)(wk + it * 32) * N_SZ + col0 + wc);
            Ws[wk + it * 32][wc + 0] = v.x;
            Ws[wk + it * 32][wc + 1] = v.y;
            Ws[wk + it * 32][wc + 2] = v.z;
            Ws[wk + it * 32][wc + 3] = v.w;
        }
    }
    __syncthreads();
    const int tr = (tid >> 4) * 4, tc = (tid & 15) * 2;
    float acc[4][2] = {};
    #pragma unroll
    for (int k = 0; k < 64; ++k) {
        float2 w = *(const float2*)&Ws[k][tc];
        float a0 = Ask[k][tr + 0], a1 = Ask[k][tr + 1];
        float a2 = Ask[k][tr + 2], a3 = Ask[k][tr + 3];
        acc[0][0] += a0 * w.x; acc[0][1] += a0 * w.y;
        acc[1][0] += a1 * w.x; acc[1][1] += a1 * w.y;
        acc[2][0] += a2 * w.x; acc[2][1] += a2 * w.y;
        acc[3][0] += a3 * w.x; acc[3][1] += a3 * w.y;
    }
    float b0 = bin[col0 + tc], b1 = bin[col0 + tc + 1];
    #pragma unroll
    for (int i = 0; i < 4; ++i) {
        size_t base = (size_t)(row0 + tr + i) * N_SZ + col0 + tc;
        g_x[base + 0] = acc[i][0] + b0;
        g_x[base + 1] = acc[i][1] + b1;
    }
}

// ---------------- persistent recurrent kernel ----------------

// one 512-K GEMM accumulation: acc[2] += (A tile 32rows) @ (W slice 32cols), f32x2 packed
__device__ __forceinline__ void mm512(const float* __restrict__ A,
                                      const float* __restrict__ W,
                                      u64* acc, float* As2, float* Ws,
                                      int row0, int col0, int tid) {
    const int pr = tid >> 3;              // A loader: row 0..31
    const int kq = (tid & 7) * 4;         // A loader: k offset
    const int m4 = (tid >> 4) * 4;        // compute: dup-pair float offset
    const int c2 = (tid & 15) * 2;        // compute: col-pair offset

    float4 ar[4], wr[4];

    // ---- load chunk 0 ----
    #pragma unroll
    for (int it = 0; it < 4; ++it)
        ar[it] = *(const float4*)(A + (size_t)(row0 + pr) * N_SZ + kq + it * 32);
    #pragma unroll
    for (int it = 0; it < 4; ++it) {
        int fl = tid + it * 256;
        int rowk = fl >> 3, c4 = (fl & 7) * 4;
        wr[it] = *(const float4*)(W + (size_t)rowk * N_SZ + col0 + c4);
    }
    // store chunk 0 -> buf 0
    #pragma unroll
    for (int it = 0; it < 4; ++it) {
        const float* v = (const float*)&ar[it];
        #pragma unroll
        for (int j = 0; j < 4; ++j) {
            float2 d = make_float2(v[j], v[j]);
            *(float2*)&As2[(kq + it * 32 + j) * A_STRIDE + 2 * pr] = d;
        }
    }
    #pragma unroll
    for (int it = 0; it < 4; ++it) {
        int fl = tid + it * 256;
        int rowk = fl >> 3, c4 = (fl & 7) * 4;
        *(float4*)&Ws[rowk * W_STRIDE + c4] = wr[it];
    }
    __syncthreads();

    #pragma unroll 1
    for (int ch = 0; ch < 4; ++ch) {
        const int buf = ch & 1;
        if (ch < 3) {
            const int c0 = (ch + 1) * KC;
            #pragma unroll
            for (int it = 0; it < 4; ++it)
                ar[it] = *(const float4*)(A + (size_t)(row0 + pr) * N_SZ + c0 + kq + it * 32);
            #pragma unroll
            for (int it = 0; it < 4; ++it) {
                int fl = tid + it * 256;
                int rowk = fl >> 3, c4 = (fl & 7) * 4;
                wr[it] = *(const float4*)(W + (size_t)(c0 + rowk) * N_SZ + col0 + c4);
            }
        }
        // ---- compute this chunk ----
        {
            const float* Ab = As2 + buf * A_BUF + m4;
            const float* Wb = Ws + buf * W_BUF + c2;
            #pragma unroll 32
            for (int k = 0; k < KC; ++k) {
                ulonglong2 aa = *(const ulonglong2*)(Ab + k * A_STRIDE);
                u64 ww = *(const u64*)(Wb + k * W_STRIDE);
                fma2(acc[0], aa.x, ww);
                fma2(acc[1], aa.y, ww);
            }
        }
        if (ch < 3) {
            const int nb = buf ^ 1;
            #pragma unroll
            for (int it = 0; it < 4; ++it) {
                const float* v = (const float*)&ar[it];
                #pragma unroll
                for (int j = 0; j < 4; ++j) {
                    float2 d = make_float2(v[j], v[j]);
                    *(float2*)&As2[nb * A_BUF + (kq + it * 32 + j) * A_STRIDE + 2 * pr] = d;
                }
            }
            #pragma unroll
            for (int it = 0; it < 4; ++it) {
                int fl = tid + it * 256;
                int rowk = fl >> 3, c4 = (fl & 7) * 4;
                *(float4*)&Ws[nb * W_BUF + rowk * W_STRIDE + c4] = wr[it];
            }
            __syncthreads();
        }
    }
}

__device__ __forceinline__ void epilogue(int layer,
                                         const float* __restrict__ hold,
                                         float* __restrict__ hnew,
                                         const u64* acc,
                                         const float* __restrict__ xrow,
                                         int row0, int col0, int tid) {
    const int tr = (tid >> 4) * 2;
    const int tc = (tid & 15) * 2;
    const float b0 = g_bias[layer * N_SZ + col0 + tc];
    const float b1 = g_bias[layer * N_SZ + col0 + tc + 1];
    #pragma unroll
    for (int i = 0; i < 2; ++i) {
        float2 s = unpack2(acc[i]);
        size_t base = (size_t)(row0 + tr + i) * N_SZ + col0 + tc;
        float h0v = hold[base], h1v = hold[base + 1];
        float x0 = xrow[base], x1 = xrow[base + 1];
        float v0 = ALPHA * h0v + (s.x + b0 + x0) * INV_TAU;
        float v1 = ALPHA * h1v + (s.y + b1 + x1) * INV_TAU;
        hnew[base]     = (v0 > 0.0f) ? v0 : SLOPE * v0;
        hnew[base + 1] = (v1 > 0.0f) ? v1 : SLOPE * v1;
    }
}

// rowblock barrier: 16 CTAs sharing the same 32-row stripe
__device__ __forceinline__ void rowbar(int rb, unsigned target) {
    __syncthreads();
    if (threadIdx.x == 0) {
        __threadfence();
        atomicAdd(&g_rb[rb], 1u);
        while (*(volatile unsigned*)&g_rb[rb] < target) { __nanosleep(32); }
        __threadfence();
    }
    __syncthreads();
}

__global__ void __launch_bounds__(256, 1) rnn_kernel() {
    extern __shared__ float sm[];
    float* As2 = sm;
    float* Ws = sm + 2 * A_BUF;

    const int bid = blockIdx.x;
    const int rb = bid >> 4;
    const int row0 = rb * 32;
    const int col0 = (bid & 15) * 32;
    const int tid = threadIdx.x;

    for (int t = 0; t < T_STEPS; ++t) {
        const int cur = t & 1, nxt = cur ^ 1;
        const float* xrow = g_x + (size_t)t * B_SZ * N_SZ;
        const unsigned base = 16u * (unsigned)(3 * t);

        // stage A: n0
        {
            u64 acc[2] = {0ull, 0ull};
            mm512(g_h[cur][0], g_W + 0 * NN, acc, As2, Ws, row0, col0, tid);
            epilogue(0, g_h[cur][0], g_h[nxt][0], acc, xrow, row0, col0, tid);
        }
        rowbar(rb, base + 16u);
        // stage B: n1
        {
            u64 acc[2] = {0ull, 0ull};
            mm512(g_h[cur][1], g_W + 1 * NN, acc, As2, Ws, row0, col0, tid);
            mm512(g_h[nxt][0], g_W + 3 * NN, acc, As2, Ws, row0, col0, tid);
            epilogue(1, g_h[cur][1], g_h[nxt][1], acc, xrow, row0, col0, tid);
        }
        rowbar(rb, base + 32u);
        // stage C: n2
        {
            u64 acc[2] = {0ull, 0ull};
            mm512(g_h[cur][2], g_W + 2 * NN, acc, As2, Ws, row0, col0, tid);
            mm512(g_h[nxt][1], g_W + 4 * NN, acc, As2, Ws, row0, col0, tid);
            epilogue(2, g_h[cur][2], g_h[nxt][2], acc, xrow, row0, col0, tid);
        }
        rowbar(rb, base + 48u);
    }
}

// ---------------- readout: warp per output ----------------
__global__ void __launch_bounds__(256) final_kernel(const float* __restrict__ Wfc,
                                                    const float* __restrict__ bfc,
                                                    float* __restrict__ out) {
    const int warp = threadIdx.x >> 5, lane = threadIdx.x & 31;
    const int idx = blockIdx.x * 8 + warp;
    if (idx >= B_SZ * C_SZ) return;
    const int b = idx / C_SZ, c = idx % C_SZ;
    const float* h2 = g_h[0][2];
    float s = 0.0f;
    #pragma unroll
    for (int i = 0; i < 16; ++i) {
        int n = lane + i * 32;
        s += h2[(size_t)b * N_SZ + n] * Wfc[n * C_SZ + c];
    }
    #pragma unroll
    for (int off = 16; off > 0; off >>= 1)
        s += __shfl_xor_sync(0xffffffffu, s, off);
    if (lane == 0) out[idx] = s + bfc[c];
}

// ---------------- launch ----------------
extern "C" void kernel_launch(void* const* d_in, const int* in_sizes, int n_in,
                              void* d_out, int out_size) {
    const float* data = nullptr; const float* h0 = nullptr;
    const float* Win = nullptr;  const float* b_in = nullptr;
    const float* Whh = nullptr;  const float* b_hh = nullptr;
    const float* Whi = nullptr;  const float* b_hi = nullptr;
    const float* Wfc = nullptr;  const float* b_fc = nullptr;
    for (int i = 0; i < n_in; ++i) {
        const float* ptr = (const float*)d_in[i];
        switch (in_sizes[i]) {
            case T_STEPS * B_SZ * I_SZ: data = ptr; break;
            case 3 * B_SZ * N_SZ:       h0 = ptr; break;
            case I_SZ * N_SZ:           Win = ptr; break;
            case N_SZ:                  b_in = ptr; break;
            case 3 * NN:                Whh = ptr; break;
            case 3 * N_SZ:              b_hh = ptr; break;
            case 2 * NN:                Whi = ptr; break;
            case 2 * N_SZ:              b_hi = ptr; break;
            case N_SZ * C_SZ:           Wfc = ptr; break;
            case C_SZ:                  b_fc = ptr; break;
            default: break;
        }
    }
    float* out = (float*)d_out;

    static bool attr_done = false;
    if (!attr_done) {
        cudaFuncSetAttribute(rnn_kernel, cudaFuncAttributeMaxDynamicSharedMemorySize,
                             SMEM_BYTES);
        attr_done = true;
    }

    prep_kernel<<<(3 * NN + 255) / 256, 256>>>(Whh, b_hh, Whi, b_hi, h0);
    xproj_kernel<<<dim3((T_STEPS * B_SZ) / 64, N_SZ / 32), 256>>>(data, Win, b_in);
    rnn_kernel<<<G_CTAS, 256, SMEM_BYTES>>>();
    final_kernel<<<(B_SZ * C_SZ + 7) / 8, 256>>>(Wfc, b_fc, out);
}

// round 5
// speedup vs baseline: 2.6239x; 2.6239x over previous
#include <cuda_runtime.h>
#include <cuda_fp16.h>
#include <cstdint>
#include <cstddef>

#define T_STEPS 512
#define B_SZ 256
#define I_SZ 64
#define N_SZ 512
#define C_SZ 10
#define NN (N_SZ * N_SZ)

// ---------------- device globals ----------------
__device__ float g_x[(size_t)T_STEPS * B_SZ * N_SZ];
__device__ float g_bias[3][N_SZ];
__device__ float g_h2[B_SZ * N_SZ];
// A packs: [buf 2][layer 3][mg 16][k16 32][lane 32][slot 8 x 4B]  (hi slots 0-3, lo 4-7)
__device__ __align__(16) char g_Ap[(size_t)2 * 3 * 16 * 32 * 32 * 32];
// B packs: [w 5][ng 64][k16 32][lane 32][slot 4 x 4B]  (b0h b1h b0l b1l)
__device__ __align__(16) char g_Bp[(size_t)5 * 64 * 32 * 32 * 16];
__device__ unsigned g_bar[24];   // [rb 8][stage 3]

// ---------------- mma helper (sm_80 base feature, no "a" suffix) ----------------
__device__ __forceinline__ void mma16816(float* d, uint4 a, uint32_t b0, uint32_t b1) {
    asm("mma.sync.aligned.m16n8k16.row.col.f32.f16.f16.f32 "
        "{%0,%1,%2,%3}, {%4,%5,%6,%7}, {%8,%9}, {%0,%1,%2,%3};"
        : "+f"(d[0]), "+f"(d[1]), "+f"(d[2]), "+f"(d[3])
        : "r"(a.x), "r"(a.y), "r"(a.z), "r"(a.w), "r"(b0), "r"(b1));
}

__device__ __forceinline__ void gemmw(float* acc, const char* A, const char* B) {
    #pragma unroll 4
    for (int ks = 0; ks < 32; ++ks) {
        uint4 ah = *(const uint4*)(A + ks * 1024);
        uint4 al = *(const uint4*)(A + ks * 1024 + 16);
        uint4 b  = *(const uint4*)(B + ks * 512);
        mma16816(acc, ah, b.x, b.y);   // Ah*Bh
        mma16816(acc, ah, b.z, b.w);   // Ah*Bl
        mma16816(acc, al, b.x, b.y);   // Al*Bh
    }
}

__device__ __forceinline__ const char* apb(int buf, int layer, int mg, int lane) {
    return g_Ap + (((size_t)(buf * 3 + layer) * 16 + mg) * 32768) + lane * 32;
}
__device__ __forceinline__ const char* bpb(int w, int ng, int lane) {
    return g_Bp + ((size_t)(w * 64 + ng) * 16384) + lane * 16;
}

// ---------------- prep: pack weights + initial states ----------------
__global__ void prep_kernel(const float* __restrict__ Whh, const float* __restrict__ bhh,
                            const float* __restrict__ Whi, const float* __restrict__ bhi,
                            const float* __restrict__ h0) {
    int idx = blockIdx.x * blockDim.x + threadIdx.x;
    if (idx < 5 * NN) {
        int w = idx / NN, rem = idx % NN;
        int k = rem / N_SZ, n = rem % N_SZ;
        float val = (w < 3)
            ? ((k == n) ? 0.0f : Whh[(size_t)w * NN + (size_t)k * N_SZ + n])
            : Whi[(size_t)(w - 3) * NN + (size_t)k * N_SZ + n];
        __half hi = __float2half_rn(val);
        __half lo = __float2half_rn(val - __half2float(hi));
        int ng = n >> 3, gid = n & 7;
        int k16 = k >> 4, kw = k & 15;
        int tig = (kw & 7) >> 1;
        int lane = (gid << 2) | tig;
        int breg = (kw >= 8) ? 1 : 0;
        char* base = g_Bp + (((size_t)(w * 64 + ng) * 32 + k16) * 32 + lane) * 16;
        *(__half*)(base + breg * 4 + (kw & 1) * 2) = hi;
        *(__half*)(base + (breg + 2) * 4 + (kw & 1) * 2) = lo;
    }
    if (idx < 3 * B_SZ * N_SZ) {
        int l = idx / (B_SZ * N_SZ), rem = idx % (B_SZ * N_SZ);
        int m = rem / N_SZ, n = rem % N_SZ;
        float val = h0[idx];
        __half hi = __float2half_rn(val);
        __half lo = __float2half_rn(val - __half2float(hi));
        int mg = m >> 4, rw = m & 15;
        int k16 = n >> 4, kw = n & 15;
        int lane = ((rw & 7) << 2) | ((kw & 7) >> 1);
        int slot = ((rw >= 8) ? 1 : 0) + ((kw >= 8) ? 2 : 0);
        char* base = g_Ap + (((size_t)(0 * 3 + l) * 16 + mg) * 32 + k16) * 1024 + lane * 32;
        *(__half*)(base + slot * 4 + (kw & 1) * 2) = hi;
        *(__half*)(base + (slot + 4) * 4 + (kw & 1) * 2) = lo;
    }
    if (idx < 3 * N_SZ) {
        int l = idx / N_SZ, c = idx % N_SZ;
        float b = bhh[idx];
        if (l >= 1) b += bhi[(l - 1) * N_SZ + c];
        g_bias[l][c] = b;
    }
    if (idx < 24) g_bar[idx] = 0;
}

// ---------------- input projection ----------------
__global__ void __launch_bounds__(256) xproj_kernel(const float* __restrict__ data,
                                                    const float* __restrict__ Win,
                                                    const float* __restrict__ bin) {
    __shared__ float Ask[64][65];
    __shared__ float Ws[64][34];
    const int row0 = blockIdx.x * 64, col0 = blockIdx.y * 32, tid = threadIdx.x;
    {
        int ar = tid >> 2, ak = (tid & 3) * 4;
        #pragma unroll
        for (int it = 0; it < 4; ++it) {
            float4 v = *(const float4*)(data + (size_t)(row0 + ar) * I_SZ + ak + it * 16);
            Ask[ak + it * 16 + 0][ar] = v.x; Ask[ak + it * 16 + 1][ar] = v.y;
            Ask[ak + it * 16 + 2][ar] = v.z; Ask[ak + it * 16 + 3][ar] = v.w;
        }
    }
    {
        int wk = tid >> 3, wc = (tid & 7) * 4;
        #pragma unroll
        for (int it = 0; it < 2; ++it) {
            float4 v = *(const float4*)(Win + (size_t)(wk + it * 32) * N_SZ + col0 + wc);
            Ws[wk + it * 32][wc + 0] = v.x; Ws[wk + it * 32][wc + 1] = v.y;
            Ws[wk + it * 32][wc + 2] = v.z; Ws[wk + it * 32][wc + 3] = v.w;
        }
    }
    __syncthreads();
    const int tr = (tid >> 4) * 4, tc = (tid & 15) * 2;
    float acc[4][2] = {};
    #pragma unroll
    for (int k = 0; k < 64; ++k) {
        float2 w = *(const float2*)&Ws[k][tc];
        float a0 = Ask[k][tr], a1 = Ask[k][tr + 1], a2 = Ask[k][tr + 2], a3 = Ask[k][tr + 3];
        acc[0][0] += a0 * w.x; acc[0][1] += a0 * w.y;
        acc[1][0] += a1 * w.x; acc[1][1] += a1 * w.y;
        acc[2][0] += a2 * w.x; acc[2][1] += a2 * w.y;
        acc[3][0] += a3 * w.x; acc[3][1] += a3 * w.y;
    }
    float b0 = bin[col0 + tc], b1 = bin[col0 + tc + 1];
    #pragma unroll
    for (int i = 0; i < 4; ++i) {
        size_t base = (size_t)(row0 + tr + i) * N_SZ + col0 + tc;
        g_x[base] = acc[i][0] + b0;
        g_x[base + 1] = acc[i][1] + b1;
    }
}

// ---------------- barriers ----------------
__device__ __forceinline__ void bar_arrive(int rb, int j) {
    __syncthreads();
    if (threadIdx.x == 0) { __threadfence(); atomicAdd(&g_bar[rb * 3 + j], 1u); }
}
__device__ __forceinline__ void bar_wait(int rb, int j, unsigned target) {
    if (threadIdx.x == 0) {
        while (*(volatile unsigned*)&g_bar[rb * 3 + j] < target) __nanosleep(32);
        __threadfence();
    }
    __syncthreads();
}

// ---------------- epilogue ----------------
__device__ __forceinline__ void epilogue(int s, int t, int nxt, const float* acc,
                                         float* hr, const float* bv,
                                         int m0, int nc, int mg, int k16w,
                                         int sl0, int lane, bool last) {
    const float* xp = g_x + ((size_t)t * B_SZ + m0) * N_SZ + nc;
    float2 xa = *(const float2*)xp;
    float2 xb = *(const float2*)(xp + 8 * N_SZ);
    float v0 = 0.5f * hr[0] + 0.5f * (acc[0] + bv[0] + xa.x);
    float v1 = 0.5f * hr[1] + 0.5f * (acc[1] + bv[1] + xa.y);
    float v2 = 0.5f * hr[2] + 0.5f * (acc[2] + bv[0] + xb.x);
    float v3 = 0.5f * hr[3] + 0.5f * (acc[3] + bv[1] + xb.y);
    v0 = (v0 > 0.0f) ? v0 : 0.01f * v0;
    v1 = (v1 > 0.0f) ? v1 : 0.01f * v1;
    v2 = (v2 > 0.0f) ? v2 : 0.01f * v2;
    v3 = (v3 > 0.0f) ? v3 : 0.01f * v3;
    hr[0] = v0; hr[1] = v1; hr[2] = v2; hr[3] = v3;

    __half h0v = __float2half_rn(v0), h1v = __float2half_rn(v1);
    __half h2v = __float2half_rn(v2), h3v = __float2half_rn(v3);
    __half l0v = __float2half_rn(v0 - __half2float(h0v));
    __half l1v = __float2half_rn(v1 - __half2float(h1v));
    __half l2v = __float2half_rn(v2 - __half2float(h2v));
    __half l3v = __float2half_rn(v3 - __half2float(h3v));
    uint32_t hi01 = (uint32_t)__half_as_ushort(h0v) | ((uint32_t)__half_as_ushort(h1v) << 16);
    uint32_t hi23 = (uint32_t)__half_as_ushort(h2v) | ((uint32_t)__half_as_ushort(h3v) << 16);
    uint32_t lo01 = (uint32_t)__half_as_ushort(l0v) | ((uint32_t)__half_as_ushort(l1v) << 16);
    uint32_t lo23 = (uint32_t)__half_as_ushort(l2v) | ((uint32_t)__half_as_ushort(l3v) << 16);

    char* base = g_Ap + (((size_t)(nxt * 3 + s) * 16 + mg) * 32 + k16w) * 1024 + lane * 32;
    *(uint32_t*)(base + sl0 * 4) = hi01;
    *(uint32_t*)(base + (sl0 + 1) * 4) = hi23;
    *(uint32_t*)(base + (sl0 + 4) * 4) = lo01;
    *(uint32_t*)(base + (sl0 + 5) * 4) = lo23;

    if (last) {
        float* o = g_h2 + (size_t)m0 * N_SZ + nc;
        o[0] = v0; o[1] = v1;
        o[8 * N_SZ] = v2; o[8 * N_SZ + 1] = v3;
    }
}

// ---------------- persistent HMMA recurrent kernel ----------------
__global__ void __launch_bounds__(256, 1) rnn_kernel(const float* __restrict__ h0) {
    const int tid = threadIdx.x;
    const int lane = tid & 31, wid = tid >> 5;
    const int wm = wid >> 2, wn = wid & 3;
    const int gid = lane >> 2, tig = lane & 3;
    const int rb = blockIdx.x >> 4, nt = blockIdx.x & 15;
    const int m0 = rb * 32 + wm * 16 + gid;
    const int nc = nt * 32 + wn * 8 + 2 * tig;
    const int mg = rb * 2 + wm;
    const int k16w = nt * 2 + (wn >> 1);
    const int sl0 = (wn & 1) * 2;
    const int ng = nt * 4 + wn;

    float bv[3][2];
    float hr[3][4];
    #pragma unroll
    for (int s = 0; s < 3; ++s) {
        bv[s][0] = g_bias[s][nc];
        bv[s][1] = g_bias[s][nc + 1];
        const float* hp = h0 + ((size_t)s * B_SZ + m0) * N_SZ + nc;
        hr[s][0] = hp[0]; hr[s][1] = hp[1];
        hr[s][2] = hp[8 * N_SZ]; hr[s][3] = hp[8 * N_SZ + 1];
    }

    for (int t = 0; t < T_STEPS; ++t) {
        const int cur = t & 1, nxt = cur ^ 1;
        // ---- stage A: n0 = f(h0, h0@W0) ----
        {
            float acc[4] = {0.f, 0.f, 0.f, 0.f};
            gemmw(acc, apb(cur, 0, mg, lane), bpb(0, ng, lane));
            epilogue(0, t, nxt, acc, hr[0], bv[0], m0, nc, mg, k16w, sl0, lane, false);
            bar_arrive(rb, 0);
        }
        // ---- stage B: n1 = f(h1, h1@W1 + n0@Wi0) ----
        {
            float acc[4] = {0.f, 0.f, 0.f, 0.f};
            bar_wait(rb, 1, 16u * (unsigned)t);
            gemmw(acc, apb(cur, 1, mg, lane), bpb(1, ng, lane));
            bar_wait(rb, 0, 16u * (unsigned)(t + 1));
            gemmw(acc, apb(nxt, 0, mg, lane), bpb(3, ng, lane));
            epilogue(1, t, nxt, acc, hr[1], bv[1], m0, nc, mg, k16w, sl0, lane, false);
            bar_arrive(rb, 1);
        }
        // ---- stage C: n2 = f(h2, h2@W2 + n1@Wi1) ----
        {
            float acc[4] = {0.f, 0.f, 0.f, 0.f};
            bar_wait(rb, 2, 16u * (unsigned)t);
            gemmw(acc, apb(cur, 2, mg, lane), bpb(2, ng, lane));
            bar_wait(rb, 1, 16u * (unsigned)(t + 1));
            gemmw(acc, apb(nxt, 1, mg, lane), bpb(4, ng, lane));
            epilogue(2, t, nxt, acc, hr[2], bv[2], m0, nc, mg, k16w, sl0, lane,
                     t == T_STEPS - 1);
            bar_arrive(rb, 2);
        }
    }
}

// ---------------- readout ----------------
__global__ void __launch_bounds__(256) final_kernel(const float* __restrict__ Wfc,
                                                    const float* __restrict__ bfc,
                                                    float* __restrict__ out) {
    const int warp = threadIdx.x >> 5, lane = threadIdx.x & 31;
    const int idx = blockIdx.x * 8 + warp;
    if (idx >= B_SZ * C_SZ) return;
    const int b = idx / C_SZ, c = idx % C_SZ;
    float s = 0.0f;
    #pragma unroll
    for (int i = 0; i < 16; ++i) {
        int n = lane + i * 32;
        s += g_h2[(size_t)b * N_SZ + n] * Wfc[n * C_SZ + c];
    }
    #pragma unroll
    for (int off = 16; off > 0; off >>= 1)
        s += __shfl_xor_sync(0xffffffffu, s, off);
    if (lane == 0) out[idx] = s + bfc[c];
}

// ---------------- launch ----------------
extern "C" void kernel_launch(void* const* d_in, const int* in_sizes, int n_in,
                              void* d_out, int out_size) {
    const float* data = nullptr; const float* h0 = nullptr;
    const float* Win = nullptr;  const float* b_in = nullptr;
    const float* Whh = nullptr;  const float* b_hh = nullptr;
    const float* Whi = nullptr;  const float* b_hi = nullptr;
    const float* Wfc = nullptr;  const float* b_fc = nullptr;
    for (int i = 0; i < n_in; ++i) {
        const float* p = (const float*)d_in[i];
        switch (in_sizes[i]) {
            case T_STEPS * B_SZ * I_SZ: data = p; break;
            case 3 * B_SZ * N_SZ:       h0 = p; break;
            case I_SZ * N_SZ:           Win = p; break;
            case N_SZ:                  b_in = p; break;
            case 3 * NN:                Whh = p; break;
            case 3 * N_SZ:              b_hh = p; break;
            case 2 * NN:                Whi = p; break;
            case 2 * N_SZ:              b_hi = p; break;
            case N_SZ * C_SZ:           Wfc = p; break;
            case C_SZ:                  b_fc = p; break;
            default: break;
        }
    }
    float* out = (float*)d_out;

    prep_kernel<<<(5 * NN + 255) / 256, 256>>>(Whh, b_hh, Whi, b_hi, h0);
    xproj_kernel<<<dim3((T_STEPS * B_SZ) / 64, N_SZ / 32), 256>>>(data, Win, b_in);
    rnn_kernel<<<128, 256>>>(h0);
    final_kernel<<<(B_SZ * C_SZ + 7) / 8, 256>>>(Wfc, b_fc, out);
}